// round 2
// baseline (speedup 1.0000x reference)
#include <cuda_runtime.h>

// ---------------------------------------------------------------------------
// SparseMaxPool fused pipeline for sm_100a
//   B=16, D=512, N=64, ODIM=512, NHEADS=8
//   out layout (float32): [boundary | local | content | mask]
//     boundary: 16*512*64*64 = 33,554,432 floats @ offset 0
//     local:    @ 33,554,432
//     content:  @ 67,108,864
//     mask:     16*64*64 @ 100,663,296  (0.0/1.0)
// ---------------------------------------------------------------------------

#define NBATCH 16
#define DDIM   512
#define NSEQ   64

// scratch (allocation-free: __device__ globals)
__device__ float g_mk[NBATCH * NSEQ * 512];   // 2 MB
__device__ float g_mq[NBATCH * NSEQ * 512];   // 2 MB
__device__ float g_w [NBATCH * NSEQ * NSEQ];  // 256 KB, holds 1 + softmax(m2m)

// ---------------------------------------------------------------------------
// K1: m_k = F @ w_v^T + b_v ;  m_q = F @ w_c[:512]^T + b_c[:512]
//     F[b*64+n][d] = x[b][d][n]   (x is (B, D, N))
//     grid: (16 otile, 16 rtile=b), 256 thr, 64x64 tile, BK=16, 4x4/thread
// ---------------------------------------------------------------------------
__global__ __launch_bounds__(256) void gemm_kq(
    const float* __restrict__ x,
    const float* __restrict__ w_c, const float* __restrict__ b_c,
    const float* __restrict__ w_v, const float* __restrict__ b_v)
{
    __shared__ float As[16 * 64];   // [k][m]  (flat == contiguous x chunk)
    __shared__ float Bs[16 * 72];   // [k][o], padded stride 72

    const int tid   = threadIdx.x;
    const int otile = blockIdx.x;   // 0..7 -> m_k, 8..15 -> m_q
    const int rtile = blockIdx.y;   // == batch b (r = b*64 + n)
    const bool is_q = (otile >= 8);
    const float* Wm   = is_q ? w_c : w_v;
    const float* bias = is_q ? b_c : b_v;
    float*       outp = is_q ? g_mq : g_mk;
    const int o0 = (otile & 7) * 64;

    const int tx = tid & 15;        // o dim (4 cols each)
    const int ty = tid >> 4;        // n dim (4 rows each)

    float acc[4][4];
#pragma unroll
    for (int i = 0; i < 4; i++)
#pragma unroll
        for (int j = 0; j < 4; j++) acc[i][j] = 0.f;

    const float* Ag = x + rtile * (DDIM * NSEQ);  // batch base; chunk x[b,k0:k0+16,:] is contiguous
    const int oRow = tid >> 2;      // 0..63
    const int kq   = tid & 3;       // 0..3 (float4 of k)

    for (int k0 = 0; k0 < 512; k0 += 16) {
        float4 av = *(const float4*)(Ag + k0 * 64 + tid * 4);
        float4 bv = *(const float4*)(Wm + (o0 + oRow) * 512 + k0 + kq * 4);
        __syncthreads();
        *(float4*)(As + tid * 4) = av;
        Bs[(kq * 4 + 0) * 72 + oRow] = bv.x;
        Bs[(kq * 4 + 1) * 72 + oRow] = bv.y;
        Bs[(kq * 4 + 2) * 72 + oRow] = bv.z;
        Bs[(kq * 4 + 3) * 72 + oRow] = bv.w;
        __syncthreads();
#pragma unroll
        for (int kk = 0; kk < 16; kk++) {
            float4 a  = *(const float4*)(As + kk * 64 + ty * 4);
            float4 bb = *(const float4*)(Bs + kk * 72 + tx * 4);
            float ar[4] = {a.x, a.y, a.z, a.w};
            float br[4] = {bb.x, bb.y, bb.z, bb.w};
#pragma unroll
            for (int i = 0; i < 4; i++)
#pragma unroll
                for (int j = 0; j < 4; j++)
                    acc[i][j] += ar[i] * br[j];
        }
    }

    const int r0 = rtile * 64 + ty * 4;
    const int oc = o0 + tx * 4;
    float4 b4 = *(const float4*)(bias + oc);
#pragma unroll
    for (int i = 0; i < 4; i++) {
        float4 v;
        v.x = acc[i][0] + b4.x;
        v.y = acc[i][1] + b4.y;
        v.z = acc[i][2] + b4.z;
        v.w = acc[i][3] + b4.w;
        *(float4*)(outp + (r0 + i) * 512 + oc) = v;
    }
}

// ---------------------------------------------------------------------------
// K2: m2m[b,n,m] = (1/8) * dot(m_k[b,n], m_q[b,m]);  g_w = 1 + softmax_m
//     grid: 64 blocks = (b, 16-row chunk), 256 thr
// ---------------------------------------------------------------------------
__global__ __launch_bounds__(256) void m2m_softmax()
{
    __shared__ float As[16 * 512];  // MK rows n0..n0+15  (32 KB)
    __shared__ float Bs[64 * 33];   // MQ tile [m][kk], stride 33 (conflict-free)
    __shared__ float sm[16 * 64];   // m2m tile

    const int tid = threadIdx.x;
    const int b   = blockIdx.x >> 2;
    const int n0  = (blockIdx.x & 3) * 16;

    const float* mkp = g_mk + (b * 64 + n0) * 512;   // contiguous 8192 floats
#pragma unroll
    for (int s = 0; s < 8; s++)
        *(float4*)(As + (tid + s * 256) * 4) = *(const float4*)(mkp + (tid + s * 256) * 4);

    const int c  = tid & 63;   // m
    const int rg = tid >> 6;   // row group (4 rows each)
    float acc[4] = {0.f, 0.f, 0.f, 0.f};

    const float* mqp = g_mq + b * 64 * 512;
    const int mrow = tid >> 3;        // 0..31
    const int kq4  = (tid & 7) * 4;   // 0,4,...,28

    for (int k0 = 0; k0 < 512; k0 += 32) {
        __syncthreads();
#pragma unroll
        for (int s = 0; s < 2; s++) {
            int m = mrow + s * 32;
            float4 v = *(const float4*)(mqp + m * 512 + k0 + kq4);
            Bs[m * 33 + kq4 + 0] = v.x;
            Bs[m * 33 + kq4 + 1] = v.y;
            Bs[m * 33 + kq4 + 2] = v.z;
            Bs[m * 33 + kq4 + 3] = v.w;
        }
        __syncthreads();
#pragma unroll
        for (int kk = 0; kk < 32; kk++) {
            float bvv = Bs[c * 33 + kk];
#pragma unroll
            for (int i = 0; i < 4; i++)
                acc[i] += As[(rg * 4 + i) * 512 + k0 + kk] * bvv;
        }
    }

    __syncthreads();
#pragma unroll
    for (int i = 0; i < 4; i++)
        sm[(rg * 4 + i) * 64 + c] = acc[i] * 0.125f;   // scale = 1/sqrt(64)
    __syncthreads();

    // softmax over m (row-wise), warp w handles rows 2w, 2w+1
    const int wid = tid >> 5, lane = tid & 31;
#pragma unroll
    for (int t = 0; t < 2; t++) {
        int rr = wid * 2 + t;
        float v0 = sm[rr * 64 + lane];
        float v1 = sm[rr * 64 + lane + 32];
        float mx = fmaxf(v0, v1);
#pragma unroll
        for (int off = 16; off; off >>= 1)
            mx = fmaxf(mx, __shfl_xor_sync(0xffffffffu, mx, off));
        float e0 = __expf(v0 - mx), e1 = __expf(v1 - mx);
        float s = e0 + e1;
#pragma unroll
        for (int off = 16; off; off >>= 1)
            s += __shfl_xor_sync(0xffffffffu, s, off);
        float inv = 1.0f / s;
        g_w[(b * 64 + n0 + rr) * 64 + lane]      = 1.0f + e0 * inv;
        g_w[(b * 64 + n0 + rr) * 64 + lane + 32] = 1.0f + e1 * inv;
    }
}

// ---------------------------------------------------------------------------
// K3: materialize boundary/local/content/mask
//   - content[b,d,i,j] = max(x[b,d,i..j])  (sparse-table range-max, O(1)/query)
//   - mask membership is pure arithmetic on (o = j-i, i)
//   grid: (32 d-tiles, 16 b), 256 thr; each block: 16 d-rows -> 768 KB stores
// ---------------------------------------------------------------------------
__device__ __forceinline__ bool mask_hit(int o, int i)
{
    // group0: o in [1,15], any i
    // group1: o odd in [17,31], i even
    // group2: o = 35,39,...,63 (o%4==3, o>=35), i % 4 == 0
    return (o >= 1) && ((o <= 15)
        || ((o & 1) && (o <= 31) && !(i & 1))
        || (((o & 3) == 3) && (o >= 35) && !(i & 3)));
}

__global__ __launch_bounds__(256) void writer(
    const float* __restrict__ x, float* __restrict__ out)
{
    __shared__ float wsh[4096];          // 1 + m2m_w for this batch (16 KB)
    __shared__ float rmax[16][7][64];    // sparse table per d-row (28 KB)

    const int tid = threadIdx.x;
    const int b   = blockIdx.y;
    const int d0  = blockIdx.x * 16;

#pragma unroll
    for (int s = 0; s < 4; s++)
        *(float4*)(wsh + (tid + s * 256) * 4) =
            *(const float4*)(g_w + b * 4096 + (tid + s * 256) * 4);

    // level-0: load x[b, d0:d0+16, :] (contiguous 1024 floats)
    {
        const float* xp = x + (b * DDIM + d0) * NSEQ;
        float4 v = *(const float4*)(xp + tid * 4);
        int f = tid * 4;                       // dd = f>>6, i = f&63 (4 | 64, no wrap)
        *(float4*)&rmax[f >> 6][0][f & 63] = v;
    }
    __syncthreads();

    // build sparse table levels 1..6
#pragma unroll
    for (int k = 1; k < 7; k++) {
        int half = 1 << (k - 1);
#pragma unroll
        for (int s = 0; s < 4; s++) {
            int f = tid + s * 256;
            int dd = f >> 6, i = f & 63;
            int i2 = i + half; if (i2 > 63) i2 = 63;
            rmax[dd][k][i] = fmaxf(rmax[dd][k - 1][i], rmax[dd][k - 1][i2]);
        }
        __syncthreads();
    }

    float* outB = out;
    float* outL = out + 33554432;
    float* outC = out + 67108864;

    for (int dd = 0; dd < 16; dd++) {
        const float* rm0 = rmax[dd][0];
        const int base = (b * 512 + d0 + dd) << 12;   // *4096
#pragma unroll
        for (int ch = 0; ch < 4; ch++) {
            const int p0 = (ch * 256 + tid) * 4;
            const int i  = p0 >> 6;                   // row (4 | 64 -> same i for p0..p0+3)
            float4 vb, vl, vc;
#pragma unroll
            for (int q = 0; q < 4; q++) {
                int p = p0 + q;
                int j = p & 63;
                int o = j - i;
                float W = wsh[p];
                float rb, rl, rc;
                if (o == 0) {
                    float v = rm0[i] * W;
                    rb = rl = rc = v;
                } else if (mask_hit(o, i)) {
                    float xi = rm0[i], xj = rm0[j];
                    float s2 = xi + xj;
                    rb = s2 * 0.5f * W;
                    rl = (s2 + 0.5f * rm0[(i + j) >> 1]) * 0.4f * W;
                    int span = o + 1;
                    int k = 31 - __clz(span);
                    rc = fmaxf(rmax[dd][k][i], rmax[dd][k][j - (1 << k) + 1]) * W;
                } else {
                    rb = rl = rc = 0.f;
                }
                ((float*)&vb)[q] = rb;
                ((float*)&vl)[q] = rl;
                ((float*)&vc)[q] = rc;
            }
            *(float4*)(outB + base + p0) = vb;
            *(float4*)(outL + base + p0) = vl;
            *(float4*)(outC + base + p0) = vc;
        }
    }

    // mask (float 0/1), one set of blocks per batch
    if (blockIdx.x == 0) {
        float* outM = out + 100663296 + b * 4096;
#pragma unroll
        for (int s = 0; s < 4; s++) {
            int p0 = (s * 256 + tid) * 4;
            int i = p0 >> 6;
            float4 v;
#pragma unroll
            for (int q = 0; q < 4; q++) {
                int j = (p0 + q) & 63;
                int o = j - i;
                bool on = (o == 0) || mask_hit(o, i);
                ((float*)&v)[q] = on ? 1.0f : 0.0f;
            }
            *(float4*)(outM + p0) = v;
        }
    }
}

// ---------------------------------------------------------------------------
extern "C" void kernel_launch(void* const* d_in, const int* in_sizes, int n_in,
                              void* d_out, int out_size)
{
    const float* x   = (const float*)d_in[0];
    const float* w_c = (const float*)d_in[1];
    const float* b_c = (const float*)d_in[2];
    const float* w_v = (const float*)d_in[3];
    const float* b_v = (const float*)d_in[4];
    float* out = (float*)d_out;

    gemm_kq<<<dim3(16, 16), 256>>>(x, w_c, b_c, w_v, b_v);
    m2m_softmax<<<64, 256>>>();
    writer<<<dim3(32, 16), 256>>>(x, out);
}

// round 3
// speedup vs baseline: 1.2491x; 1.2491x over previous
#include <cuda_runtime.h>
#include <cstdint>

// ---------------------------------------------------------------------------
// SparseMaxPool fused pipeline for sm_100a
//   B=16, D=512, N=64, ODIM=512, NHEADS=8
//   out layout (float32): [boundary | local | content | mask]
// ---------------------------------------------------------------------------

#define NBATCH 16
#define DDIM   512
#define NSEQ   64

// scratch (allocation-free: __device__ globals)
__device__ float g_mk[NBATCH * 64 * 512];   // 2 MB
__device__ float g_mq[NBATCH * 64 * 512];   // 2 MB
__device__ float g_w [NBATCH * 64 * 64];    // 256 KB, holds 1 + softmax(m2m)

// ---------------------------------------------------------------------------
// tf32 helpers (warp-level mma.sync, m16n8k8, row.col, fp32 accum)
// ---------------------------------------------------------------------------
__device__ __forceinline__ unsigned f2tf(float f) {
    unsigned r;
    asm("cvt.rna.tf32.f32 %0, %1;" : "=r"(r) : "f"(f));
    return r;
}
__device__ __forceinline__ void mma_tf32(float c[4],
    unsigned a0, unsigned a1, unsigned a2, unsigned a3,
    unsigned b0, unsigned b1)
{
    asm volatile(
        "mma.sync.aligned.m16n8k8.row.col.f32.tf32.tf32.f32 "
        "{%0,%1,%2,%3}, {%4,%5,%6,%7}, {%8,%9}, {%0,%1,%2,%3};"
        : "+f"(c[0]), "+f"(c[1]), "+f"(c[2]), "+f"(c[3])
        : "r"(a0), "r"(a1), "r"(a2), "r"(a3), "r"(b0), "r"(b1));
}

// ---------------------------------------------------------------------------
// K1: C[1024 x 1024] = F[1024 x 512] @ W[1024 x 512]^T  (tf32 tensor cores)
//   rows r = b*64+n  (F[r][k] = x[b][k][n], so the x chunk is [k][m] layout)
//   cols o: 0-511 -> m_k (w_v/b_v), 512-1023 -> m_q (w_c/b_c, first 512 rows)
//   grid (16 otile, 16 batch), 128 thr (4 warps), block tile 64x64, K-chunk 32
// ---------------------------------------------------------------------------
__global__ __launch_bounds__(128) void gemm_kq(
    const float* __restrict__ x,
    const float* __restrict__ w_c, const float* __restrict__ b_c,
    const float* __restrict__ w_v, const float* __restrict__ b_v)
{
    __shared__ float As[32 * 64];   // [k][m ^ ((k&3)<<3)]  (swizzled, conflict-free frags)
    __shared__ float Bs[64 * 36];   // [o][k], pitch 36 (conflict-free frags)

    const int tid  = threadIdx.x;
    const int lane = tid & 31, wid = tid >> 5;
    const int gid  = lane >> 2, tig = lane & 3;
    const int bx = blockIdx.x, by = blockIdx.y;

    const float* Wm   = (bx < 8) ? w_v : w_c;
    const float* bias = (bx < 8) ? b_v : b_c;
    float*       outp = (bx < 8) ? g_mk : g_mq;
    const int o0 = (bx & 7) * 64;

    const int wm = (wid & 1) * 32;   // warp tile 32x32
    const int wn = (wid >> 1) * 32;

    const float* xb = x + by * (DDIM * NSEQ);

    float acc[2][4][4];
#pragma unroll
    for (int mi = 0; mi < 2; mi++)
#pragma unroll
        for (int ni = 0; ni < 4; ni++)
#pragma unroll
            for (int t = 0; t < 4; t++) acc[mi][ni][t] = 0.f;

    float4 pA[4], pB[4];

#define K1_LDG(k0)                                                              \
    {                                                                           \
        _Pragma("unroll")                                                       \
        for (int s = 0; s < 4; s++) {                                           \
            pA[s] = *(const float4*)(xb + (k0) * 64 + tid * 4 + s * 512);       \
            int idx = tid + s * 128; int orow = idx >> 3, kq = idx & 7;         \
            pB[s] = *(const float4*)(Wm + (o0 + orow) * 512 + (k0) + kq * 4);   \
        }                                                                       \
    }

    K1_LDG(0)

    for (int c = 0; c < 16; c++) {
        __syncthreads();
#pragma unroll
        for (int s = 0; s < 4; s++) {
            int f = tid * 4 + s * 512;
            int k = f >> 6, m = f & 63;
            *(float4*)(As + k * 64 + (m ^ ((k & 3) << 3))) = pA[s];
            int idx = tid + s * 128; int orow = idx >> 3, kq = idx & 7;
            *(float4*)(Bs + orow * 36 + kq * 4) = pB[s];
        }
        __syncthreads();
        if (c < 15) { int k0n = (c + 1) * 32; K1_LDG(k0n) }

#pragma unroll
        for (int ks = 0; ks < 4; ks++) {
            const int kk = ks * 8;
            const int sw = tig << 3;
            unsigned af[2][4];
#pragma unroll
            for (int mi = 0; mi < 2; mi++) {
                int mb = wm + mi * 16;
                af[mi][0] = f2tf(As[(kk + tig) * 64 + ((mb + gid) ^ sw)]);
                af[mi][1] = f2tf(As[(kk + tig) * 64 + ((mb + gid + 8) ^ sw)]);
                af[mi][2] = f2tf(As[(kk + tig + 4) * 64 + ((mb + gid) ^ sw)]);
                af[mi][3] = f2tf(As[(kk + tig + 4) * 64 + ((mb + gid + 8) ^ sw)]);
            }
#pragma unroll
            for (int ni = 0; ni < 4; ni++) {
                int nb = wn + ni * 8;
                unsigned b0 = f2tf(Bs[(nb + gid) * 36 + kk + tig]);
                unsigned b1 = f2tf(Bs[(nb + gid) * 36 + kk + tig + 4]);
#pragma unroll
                for (int mi = 0; mi < 2; mi++)
                    mma_tf32(acc[mi][ni], af[mi][0], af[mi][1], af[mi][2], af[mi][3], b0, b1);
            }
        }
    }

    // epilogue: bias + store (float2, 32B-coalesced per 4-lane group)
#pragma unroll
    for (int ni = 0; ni < 4; ni++) {
        int col = wn + ni * 8 + tig * 2;
        float2 bb = *(const float2*)(bias + o0 + col);
#pragma unroll
        for (int mi = 0; mi < 2; mi++) {
            int r = by * 64 + wm + mi * 16 + gid;
            float2 v0 = { acc[mi][ni][0] + bb.x, acc[mi][ni][1] + bb.y };
            float2 v1 = { acc[mi][ni][2] + bb.x, acc[mi][ni][3] + bb.y };
            *(float2*)(outp + r * 512 + o0 + col)       = v0;
            *(float2*)(outp + (r + 8) * 512 + o0 + col) = v1;
        }
    }
#undef K1_LDG
}

// ---------------------------------------------------------------------------
// K2: m2m[b,n,m] = 0.125 * dot(m_k[b,n], m_q[b,m]); g_w = 1 + softmax_m
//   tf32 mma: A = mk rows (row-major), B = mq rows ([m][k] == col-major k x m)
//   grid 32 = (batch, 32-row half), 128 thr, warp tile 32x16, K-chunk 64
// ---------------------------------------------------------------------------
__global__ __launch_bounds__(128) void m2m_softmax()
{
    __shared__ float Ak[32 * 68];
    __shared__ float Bq[64 * 68];
    __shared__ float sm[32 * 64];

    const int tid  = threadIdx.x;
    const int lane = tid & 31, wid = tid >> 5;
    const int gid  = lane >> 2, tig = lane & 3;
    const int b  = blockIdx.x >> 1;
    const int n0 = (blockIdx.x & 1) * 32;
    const int wn = wid * 16;

    const float* mk = g_mk + (b * 64 + n0) * 512;
    const float* mq = g_mq + b * 64 * 512;

    float acc[2][2][4];
#pragma unroll
    for (int mi = 0; mi < 2; mi++)
#pragma unroll
        for (int ni = 0; ni < 2; ni++)
#pragma unroll
            for (int t = 0; t < 4; t++) acc[mi][ni][t] = 0.f;

    float4 pA[4], pB[8];

#define K2_LDG(k0)                                                              \
    {                                                                           \
        _Pragma("unroll")                                                       \
        for (int s = 0; s < 4; s++) {                                           \
            int idx = tid + s * 128; int row = idx >> 4, kq = idx & 15;         \
            pA[s] = *(const float4*)(mk + row * 512 + (k0) + kq * 4);           \
        }                                                                       \
        _Pragma("unroll")                                                       \
        for (int s = 0; s < 8; s++) {                                           \
            int idx = tid + s * 128; int row = idx >> 4, kq = idx & 15;         \
            pB[s] = *(const float4*)(mq + row * 512 + (k0) + kq * 4);           \
        }                                                                       \
    }

    K2_LDG(0)

    for (int c = 0; c < 8; c++) {
        __syncthreads();
#pragma unroll
        for (int s = 0; s < 4; s++) {
            int idx = tid + s * 128; int row = idx >> 4, kq = idx & 15;
            *(float4*)(Ak + row * 68 + kq * 4) = pA[s];
        }
#pragma unroll
        for (int s = 0; s < 8; s++) {
            int idx = tid + s * 128; int row = idx >> 4, kq = idx & 15;
            *(float4*)(Bq + row * 68 + kq * 4) = pB[s];
        }
        __syncthreads();
        if (c < 7) { int k0n = (c + 1) * 64; K2_LDG(k0n) }

#pragma unroll
        for (int ks = 0; ks < 8; ks++) {
            const int kk = ks * 8;
            unsigned af[2][4];
#pragma unroll
            for (int mi = 0; mi < 2; mi++) {
                int mb = mi * 16;
                af[mi][0] = f2tf(Ak[(mb + gid) * 68 + kk + tig]);
                af[mi][1] = f2tf(Ak[(mb + gid + 8) * 68 + kk + tig]);
                af[mi][2] = f2tf(Ak[(mb + gid) * 68 + kk + tig + 4]);
                af[mi][3] = f2tf(Ak[(mb + gid + 8) * 68 + kk + tig + 4]);
            }
#pragma unroll
            for (int ni = 0; ni < 2; ni++) {
                int nb = wn + ni * 8;
                unsigned b0 = f2tf(Bq[(nb + gid) * 68 + kk + tig]);
                unsigned b1 = f2tf(Bq[(nb + gid) * 68 + kk + tig + 4]);
#pragma unroll
                for (int mi = 0; mi < 2; mi++)
                    mma_tf32(acc[mi][ni], af[mi][0], af[mi][1], af[mi][2], af[mi][3], b0, b1);
            }
        }
    }

    // scaled scores into smem
#pragma unroll
    for (int ni = 0; ni < 2; ni++) {
        int col = wn + ni * 8 + tig * 2;
#pragma unroll
        for (int mi = 0; mi < 2; mi++) {
            int row = mi * 16 + gid;
            sm[row * 64 + col]             = acc[mi][ni][0] * 0.125f;
            sm[row * 64 + col + 1]         = acc[mi][ni][1] * 0.125f;
            sm[(row + 8) * 64 + col]       = acc[mi][ni][2] * 0.125f;
            sm[(row + 8) * 64 + col + 1]   = acc[mi][ni][3] * 0.125f;
        }
    }
    __syncthreads();

    // row softmax: each warp handles 8 rows
#pragma unroll
    for (int t = 0; t < 8; t++) {
        int r = wid * 8 + t;
        float v0 = sm[r * 64 + lane];
        float v1 = sm[r * 64 + lane + 32];
        float mx = fmaxf(v0, v1);
#pragma unroll
        for (int off = 16; off; off >>= 1)
            mx = fmaxf(mx, __shfl_xor_sync(0xffffffffu, mx, off));
        float e0 = __expf(v0 - mx), e1 = __expf(v1 - mx);
        float s = e0 + e1;
#pragma unroll
        for (int off = 16; off; off >>= 1)
            s += __shfl_xor_sync(0xffffffffu, s, off);
        float inv = 1.0f / s;
        g_w[(b * 64 + n0 + r) * 64 + lane]      = 1.0f + e0 * inv;
        g_w[(b * 64 + n0 + r) * 64 + lane + 32] = 1.0f + e1 * inv;
    }
#undef K2_LDG
}

// ---------------------------------------------------------------------------
// K3: materialize boundary/local/content/mask
//   metadata (mask type, sparse-table offsets, W) hoisted OUT of the dd loop
// ---------------------------------------------------------------------------
__device__ __forceinline__ bool mask_hit(int o, int i)
{
    return (o >= 1) && ((o <= 15)
        || ((o & 1) && (o <= 31) && !(i & 1))
        || (((o & 3) == 3) && (o >= 35) && !(i & 3)));
}

__global__ __launch_bounds__(256) void writer(
    const float* __restrict__ x, float* __restrict__ out)
{
    __shared__ float rmax[16 * 7 * 64];   // sparse table per d-row (28 KB), [dd*448 + k*64 + i]

    const int tid = threadIdx.x;
    const int b   = blockIdx.y;
    const int d0  = blockIdx.x * 16;

    // level-0: x[b, d0:d0+16, :] is 1024 contiguous floats
    {
        const float* xp = x + (b * DDIM + d0) * NSEQ;
        float4 v = *(const float4*)(xp + tid * 4);
        int f = tid * 4;
        *(float4*)(rmax + (f >> 6) * 448 + (f & 63)) = v;
    }
    __syncthreads();

#pragma unroll
    for (int k = 1; k < 7; k++) {
        int half = 1 << (k - 1);
#pragma unroll
        for (int s = 0; s < 4; s++) {
            int f = tid + s * 256;
            int dd = f >> 6, i = f & 63;
            int i2 = i + half; if (i2 > 63) i2 = 63;
            rmax[dd * 448 + k * 64 + i] =
                fmaxf(rmax[dd * 448 + (k - 1) * 64 + i],
                      rmax[dd * 448 + (k - 1) * 64 + i2]);
        }
        __syncthreads();
    }

    float* outB = out;
    float* outL = out + 33554432;
    float* outC = out + 67108864;
    const int dbase0 = (b * 512 + d0) << 12;

#pragma unroll
    for (int ch = 0; ch < 4; ch++) {
        const int p0 = ch * 1024 + tid * 4;
        const int i  = p0 >> 6;

        float4 Wq = *(const float4*)(g_w + b * 4096 + p0);

        // hoisted per-position metadata
        int typ[4], xjo[4], xmo[4], t1o[4], t2o[4];
        float Wv[4], hW[4], qW[4];
#pragma unroll
        for (int q = 0; q < 4; q++) {
            int j = (p0 + q) & 63;
            int o = j - i;
            Wv[q] = ((const float*)&Wq)[q];
            hW[q] = 0.5f * Wv[q];
            qW[q] = 0.4f * Wv[q];
            if (o == 0) {
                typ[q] = 1; xjo[q] = i; xmo[q] = i; t1o[q] = i; t2o[q] = i;
            } else if (mask_hit(o, i)) {
                typ[q] = 2;
                xjo[q] = j;
                xmo[q] = (i + j) >> 1;
                int k = 31 - __clz(o + 1);
                t1o[q] = k * 64 + i;
                t2o[q] = k * 64 + j - (1 << k) + 1;
            } else {
                typ[q] = 0;
            }
        }
        const bool allzero = (typ[0] | typ[1] | typ[2] | typ[3]) == 0;

        for (int dd = 0; dd < 16; dd++) {
            const int base = dbase0 + (dd << 12) + p0;
            if (allzero) {
                float4 z = {0.f, 0.f, 0.f, 0.f};
                *(float4*)(outB + base) = z;
                *(float4*)(outL + base) = z;
                *(float4*)(outC + base) = z;
                continue;
            }
            const float* rt = rmax + dd * 448;
            const float xi = rt[i];
            float4 vb, vl, vc;
#pragma unroll
            for (int q = 0; q < 4; q++) {
                float rb, rl, rc;
                if (typ[q] == 2) {
                    float xj = rt[xjo[q]];
                    float xm = rt[xmo[q]];
                    float s2 = xi + xj;
                    rb = s2 * hW[q];
                    rl = fmaf(xm, 0.5f, s2) * qW[q];
                    rc = fmaxf(rt[t1o[q]], rt[t2o[q]]) * Wv[q];
                } else if (typ[q] == 1) {
                    float v = xi * Wv[q];
                    rb = rl = rc = v;
                } else {
                    rb = rl = rc = 0.f;
                }
                ((float*)&vb)[q] = rb;
                ((float*)&vl)[q] = rl;
                ((float*)&vc)[q] = rc;
            }
            *(float4*)(outB + base) = vb;
            *(float4*)(outL + base) = vl;
            *(float4*)(outC + base) = vc;
        }
    }

    // mask (float 0/1)
    if (blockIdx.x == 0) {
        float* outM = out + 100663296 + b * 4096;
#pragma unroll
        for (int s = 0; s < 4; s++) {
            int p0 = (s * 256 + tid) * 4;
            int i = p0 >> 6;
            float4 v;
#pragma unroll
            for (int q = 0; q < 4; q++) {
                int j = (p0 + q) & 63;
                int o = j - i;
                ((float*)&v)[q] = ((o == 0) || mask_hit(o, i)) ? 1.0f : 0.0f;
            }
            *(float4*)(outM + p0) = v;
        }
    }
}

// ---------------------------------------------------------------------------
extern "C" void kernel_launch(void* const* d_in, const int* in_sizes, int n_in,
                              void* d_out, int out_size)
{
    const float* x   = (const float*)d_in[0];
    const float* w_c = (const float*)d_in[1];
    const float* b_c = (const float*)d_in[2];
    const float* w_v = (const float*)d_in[3];
    const float* b_v = (const float*)d_in[4];
    float* out = (float*)d_out;

    gemm_kq<<<dim3(16, 16), 128>>>(x, w_c, b_c, w_v, b_v);
    m2m_softmax<<<32, 128>>>();
    writer<<<dim3(32, 16), 256>>>(x, out);
}

// round 4
// speedup vs baseline: 1.3400x; 1.0727x over previous
#include <cuda_runtime.h>
#include <cstdint>

// ---------------------------------------------------------------------------
// SparseMaxPool fused pipeline for sm_100a
//   B=16, D=512, N=64, ODIM=512, NHEADS=8
//   out layout (float32): [boundary | local | content | mask]
// ---------------------------------------------------------------------------

#define NBATCH 16
#define DDIM   512
#define NSEQ   64

// scratch (allocation-free: __device__ globals)
__device__ float g_mk[NBATCH * 64 * 512];   // 2 MB
__device__ float g_mq[NBATCH * 64 * 512];   // 2 MB
__device__ float g_w [NBATCH * 64 * 64];    // 256 KB, holds 1 + softmax(m2m)

// ---------------------------------------------------------------------------
// tf32 helpers
// ---------------------------------------------------------------------------
__device__ __forceinline__ unsigned f2tf(float f) {
    unsigned r;
    asm("cvt.rna.tf32.f32 %0, %1;" : "=r"(r) : "f"(f));
    return r;
}
__device__ __forceinline__ uint4 f2tf4(float4 v) {
    uint4 r;
    r.x = f2tf(v.x); r.y = f2tf(v.y); r.z = f2tf(v.z); r.w = f2tf(v.w);
    return r;
}
__device__ __forceinline__ void mma_tf32(float c[4],
    unsigned a0, unsigned a1, unsigned a2, unsigned a3,
    unsigned b0, unsigned b1)
{
    asm volatile(
        "mma.sync.aligned.m16n8k8.row.col.f32.tf32.tf32.f32 "
        "{%0,%1,%2,%3}, {%4,%5,%6,%7}, {%8,%9}, {%0,%1,%2,%3};"
        : "+f"(c[0]), "+f"(c[1]), "+f"(c[2]), "+f"(c[3])
        : "r"(a0), "r"(a1), "r"(a2), "r"(a3), "r"(b0), "r"(b1));
}

// ---------------------------------------------------------------------------
// K1: C[1024 x 1024] = F[1024 x 512] @ W[1024 x 512]^T  (tf32 tensor cores)
//   F[b*64+n][k] = x[b][k][n]  (x chunk is [k][m] layout, contiguous per b)
//   grid (8, 16): bx<4 -> m_k (w_v), bx>=4 -> m_q (w_c first 512 rows)
//   block 256 thr (8 warps, 2x4), block tile 64x128, warp tile 32x32, Kc=32
//   tf32 conversion done on the smem-STORE side (read path = raw LDS)
// ---------------------------------------------------------------------------
__global__ __launch_bounds__(256) void gemm_kq(
    const float* __restrict__ x,
    const float* __restrict__ w_c, const float* __restrict__ b_c,
    const float* __restrict__ w_v, const float* __restrict__ b_v)
{
    __shared__ unsigned As[32 * 64];    // [k][m ^ ((k&3)<<3)] tf32 bits
    __shared__ unsigned Bs[128 * 36];   // [o][k] pitch 36, tf32 bits

    const int tid  = threadIdx.x;
    const int lane = tid & 31, wid = tid >> 5;
    const int gid  = lane >> 2, tig = lane & 3;
    const int bx = blockIdx.x, by = blockIdx.y;

    const bool is_q = (bx >= 4);
    const float* Wm   = is_q ? w_c : w_v;
    const float* bias = is_q ? b_c : b_v;
    float*       outp = is_q ? g_mq : g_mk;
    const int o0 = (bx & 3) * 128;

    const int wm = (wid & 1) * 32;
    const int wn = (wid >> 1) * 32;

    const float* xb = x + by * (DDIM * NSEQ);

    float acc[2][4][4];
#pragma unroll
    for (int mi = 0; mi < 2; mi++)
#pragma unroll
        for (int ni = 0; ni < 4; ni++)
#pragma unroll
            for (int t = 0; t < 4; t++) acc[mi][ni][t] = 0.f;

    float4 pA[2], pB[4];

#define K1_LDG(k0)                                                              \
    {                                                                           \
        _Pragma("unroll")                                                       \
        for (int s = 0; s < 2; s++)                                             \
            pA[s] = *(const float4*)(xb + (k0) * 64 + tid * 4 + s * 1024);      \
        _Pragma("unroll")                                                       \
        for (int s = 0; s < 4; s++) {                                           \
            int idx = tid + s * 256; int orow = idx >> 3, kq = idx & 7;         \
            pB[s] = *(const float4*)(Wm + (o0 + orow) * 512 + (k0) + kq * 4);   \
        }                                                                       \
    }

    K1_LDG(0)

    for (int c = 0; c < 16; c++) {
        __syncthreads();
#pragma unroll
        for (int s = 0; s < 2; s++) {
            int f = tid * 4 + s * 1024;
            int k = f >> 6, m = f & 63;
            *(uint4*)(As + k * 64 + (m ^ ((k & 3) << 3))) = f2tf4(pA[s]);
        }
#pragma unroll
        for (int s = 0; s < 4; s++) {
            int idx = tid + s * 256; int orow = idx >> 3, kq = idx & 7;
            *(uint4*)(Bs + orow * 36 + kq * 4) = f2tf4(pB[s]);
        }
        __syncthreads();
        if (c < 15) { int k0n = (c + 1) * 32; K1_LDG(k0n) }

#pragma unroll
        for (int ks = 0; ks < 4; ks++) {
            const int kk = ks * 8;
            const int sw = tig << 3;
            unsigned af[2][4];
#pragma unroll
            for (int mi = 0; mi < 2; mi++) {
                int mb = wm + mi * 16;
                af[mi][0] = As[(kk + tig) * 64 + ((mb + gid) ^ sw)];
                af[mi][1] = As[(kk + tig) * 64 + ((mb + gid + 8) ^ sw)];
                af[mi][2] = As[(kk + tig + 4) * 64 + ((mb + gid) ^ sw)];
                af[mi][3] = As[(kk + tig + 4) * 64 + ((mb + gid + 8) ^ sw)];
            }
#pragma unroll
            for (int ni = 0; ni < 4; ni++) {
                int nb = wn + ni * 8;
                unsigned b0 = Bs[(nb + gid) * 36 + kk + tig];
                unsigned b1 = Bs[(nb + gid) * 36 + kk + tig + 4];
#pragma unroll
                for (int mi = 0; mi < 2; mi++)
                    mma_tf32(acc[mi][ni], af[mi][0], af[mi][1], af[mi][2], af[mi][3], b0, b1);
            }
        }
    }

    // epilogue: bias + store
#pragma unroll
    for (int ni = 0; ni < 4; ni++) {
        int col = wn + ni * 8 + tig * 2;
        float2 bb = *(const float2*)(bias + o0 + col);
#pragma unroll
        for (int mi = 0; mi < 2; mi++) {
            int r = by * 64 + wm + mi * 16 + gid;
            float2 v0 = { acc[mi][ni][0] + bb.x, acc[mi][ni][1] + bb.y };
            float2 v1 = { acc[mi][ni][2] + bb.x, acc[mi][ni][3] + bb.y };
            *(float2*)(outp + r * 512 + o0 + col)       = v0;
            *(float2*)(outp + (r + 8) * 512 + o0 + col) = v1;
        }
    }
#undef K1_LDG
}

// ---------------------------------------------------------------------------
// K2: m2m[b,n,m] = 0.125 * dot(m_k[b,n], m_q[b,m]); g_w = 1 + softmax_m
//   grid 32 = (batch, 32-row half), 128 thr, warp tile 32x16, K-chunk 64
//   tf32 conversion on the smem-store side
// ---------------------------------------------------------------------------
__global__ __launch_bounds__(128) void m2m_softmax()
{
    __shared__ unsigned Ak[32 * 68];
    __shared__ unsigned Bq[64 * 68];
    __shared__ float sm[32 * 64];

    const int tid  = threadIdx.x;
    const int lane = tid & 31, wid = tid >> 5;
    const int gid  = lane >> 2, tig = lane & 3;
    const int b  = blockIdx.x >> 1;
    const int n0 = (blockIdx.x & 1) * 32;
    const int wn = wid * 16;

    const float* mk = g_mk + (b * 64 + n0) * 512;
    const float* mq = g_mq + b * 64 * 512;

    float acc[2][2][4];
#pragma unroll
    for (int mi = 0; mi < 2; mi++)
#pragma unroll
        for (int ni = 0; ni < 2; ni++)
#pragma unroll
            for (int t = 0; t < 4; t++) acc[mi][ni][t] = 0.f;

    float4 pA[4], pB[8];

#define K2_LDG(k0)                                                              \
    {                                                                           \
        _Pragma("unroll")                                                       \
        for (int s = 0; s < 4; s++) {                                           \
            int idx = tid + s * 128; int row = idx >> 4, kq = idx & 15;         \
            pA[s] = *(const float4*)(mk + row * 512 + (k0) + kq * 4);           \
        }                                                                       \
        _Pragma("unroll")                                                       \
        for (int s = 0; s < 8; s++) {                                           \
            int idx = tid + s * 128; int row = idx >> 4, kq = idx & 15;         \
            pB[s] = *(const float4*)(mq + row * 512 + (k0) + kq * 4);           \
        }                                                                       \
    }

    K2_LDG(0)

    for (int c = 0; c < 8; c++) {
        __syncthreads();
#pragma unroll
        for (int s = 0; s < 4; s++) {
            int idx = tid + s * 128; int row = idx >> 4, kq = idx & 15;
            *(uint4*)(Ak + row * 68 + kq * 4) = f2tf4(pA[s]);
        }
#pragma unroll
        for (int s = 0; s < 8; s++) {
            int idx = tid + s * 128; int row = idx >> 4, kq = idx & 15;
            *(uint4*)(Bq + row * 68 + kq * 4) = f2tf4(pB[s]);
        }
        __syncthreads();
        if (c < 7) { int k0n = (c + 1) * 64; K2_LDG(k0n) }

#pragma unroll
        for (int ks = 0; ks < 8; ks++) {
            const int kk = ks * 8;
            unsigned af[2][4];
#pragma unroll
            for (int mi = 0; mi < 2; mi++) {
                int mb = mi * 16;
                af[mi][0] = Ak[(mb + gid) * 68 + kk + tig];
                af[mi][1] = Ak[(mb + gid + 8) * 68 + kk + tig];
                af[mi][2] = Ak[(mb + gid) * 68 + kk + tig + 4];
                af[mi][3] = Ak[(mb + gid + 8) * 68 + kk + tig + 4];
            }
#pragma unroll
            for (int ni = 0; ni < 2; ni++) {
                int nb = wn + ni * 8;
                unsigned b0 = Bq[(nb + gid) * 68 + kk + tig];
                unsigned b1 = Bq[(nb + gid) * 68 + kk + tig + 4];
#pragma unroll
                for (int mi = 0; mi < 2; mi++)
                    mma_tf32(acc[mi][ni], af[mi][0], af[mi][1], af[mi][2], af[mi][3], b0, b1);
            }
        }
    }

#pragma unroll
    for (int ni = 0; ni < 2; ni++) {
        int col = wn + ni * 8 + tig * 2;
#pragma unroll
        for (int mi = 0; mi < 2; mi++) {
            int row = mi * 16 + gid;
            sm[row * 64 + col]           = acc[mi][ni][0] * 0.125f;
            sm[row * 64 + col + 1]       = acc[mi][ni][1] * 0.125f;
            sm[(row + 8) * 64 + col]     = acc[mi][ni][2] * 0.125f;
            sm[(row + 8) * 64 + col + 1] = acc[mi][ni][3] * 0.125f;
        }
    }
    __syncthreads();

#pragma unroll
    for (int t = 0; t < 8; t++) {
        int r = wid * 8 + t;
        float v0 = sm[r * 64 + lane];
        float v1 = sm[r * 64 + lane + 32];
        float mx = fmaxf(v0, v1);
#pragma unroll
        for (int off = 16; off; off >>= 1)
            mx = fmaxf(mx, __shfl_xor_sync(0xffffffffu, mx, off));
        float e0 = __expf(v0 - mx), e1 = __expf(v1 - mx);
        float s = e0 + e1;
#pragma unroll
        for (int off = 16; off; off >>= 1)
            s += __shfl_xor_sync(0xffffffffu, s, off);
        float inv = 1.0f / s;
        g_w[(b * 64 + n0 + r) * 64 + lane]      = 1.0f + e0 * inv;
        g_w[(b * 64 + n0 + r) * 64 + lane + 32] = 1.0f + e1 * inv;
    }
#undef K2_LDG
}

// ---------------------------------------------------------------------------
// K3: materialize boundary/local/content/mask (streaming stores)
// ---------------------------------------------------------------------------
__device__ __forceinline__ bool mask_hit(int o, int i)
{
    return (o >= 1) && ((o <= 15)
        || ((o & 1) && (o <= 31) && !(i & 1))
        || (((o & 3) == 3) && (o >= 35) && !(i & 3)));
}

__global__ __launch_bounds__(256) void writer(
    const float* __restrict__ x, float* __restrict__ out)
{
    __shared__ float rmax[16 * 7 * 64];   // sparse table [dd*448 + k*64 + i]

    const int tid = threadIdx.x;
    const int b   = blockIdx.y;
    const int d0  = blockIdx.x * 16;

    {
        const float* xp = x + (b * DDIM + d0) * NSEQ;
        float4 v = *(const float4*)(xp + tid * 4);
        int f = tid * 4;
        *(float4*)(rmax + (f >> 6) * 448 + (f & 63)) = v;
    }
    __syncthreads();

#pragma unroll
    for (int k = 1; k < 7; k++) {
        int half = 1 << (k - 1);
#pragma unroll
        for (int s = 0; s < 4; s++) {
            int f = tid + s * 256;
            int dd = f >> 6, i = f & 63;
            int i2 = i + half; if (i2 > 63) i2 = 63;
            rmax[dd * 448 + k * 64 + i] =
                fmaxf(rmax[dd * 448 + (k - 1) * 64 + i],
                      rmax[dd * 448 + (k - 1) * 64 + i2]);
        }
        __syncthreads();
    }

    float* outB = out;
    float* outL = out + 33554432;
    float* outC = out + 67108864;
    const int dbase0 = (b * 512 + d0) << 12;

#pragma unroll
    for (int ch = 0; ch < 4; ch++) {
        const int p0 = ch * 1024 + tid * 4;
        const int i  = p0 >> 6;

        float4 Wq = *(const float4*)(g_w + b * 4096 + p0);

        int typ[4], xjo[4], xmo[4], t1o[4], t2o[4];
        float Wv[4], hW[4], qW[4];
#pragma unroll
        for (int q = 0; q < 4; q++) {
            int j = (p0 + q) & 63;
            int o = j - i;
            Wv[q] = ((const float*)&Wq)[q];
            hW[q] = 0.5f * Wv[q];
            qW[q] = 0.4f * Wv[q];
            if (o == 0) {
                typ[q] = 1; xjo[q] = i; xmo[q] = i; t1o[q] = i; t2o[q] = i;
            } else if (mask_hit(o, i)) {
                typ[q] = 2;
                xjo[q] = j;
                xmo[q] = (i + j) >> 1;
                int k = 31 - __clz(o + 1);
                t1o[q] = k * 64 + i;
                t2o[q] = k * 64 + j - (1 << k) + 1;
            } else {
                typ[q] = 0;
            }
        }
        const bool allzero = (typ[0] | typ[1] | typ[2] | typ[3]) == 0;

        for (int dd = 0; dd < 16; dd++) {
            const int base = dbase0 + (dd << 12) + p0;
            if (allzero) {
                float4 z = {0.f, 0.f, 0.f, 0.f};
                __stcs((float4*)(outB + base), z);
                __stcs((float4*)(outL + base), z);
                __stcs((float4*)(outC + base), z);
                continue;
            }
            const float* rt = rmax + dd * 448;
            const float xi = rt[i];
            float4 vb, vl, vc;
#pragma unroll
            for (int q = 0; q < 4; q++) {
                float rb, rl, rc;
                if (typ[q] == 2) {
                    float xj = rt[xjo[q]];
                    float xm = rt[xmo[q]];
                    float s2 = xi + xj;
                    rb = s2 * hW[q];
                    rl = fmaf(xm, 0.5f, s2) * qW[q];
                    rc = fmaxf(rt[t1o[q]], rt[t2o[q]]) * Wv[q];
                } else if (typ[q] == 1) {
                    float v = xi * Wv[q];
                    rb = rl = rc = v;
                } else {
                    rb = rl = rc = 0.f;
                }
                ((float*)&vb)[q] = rb;
                ((float*)&vl)[q] = rl;
                ((float*)&vc)[q] = rc;
            }
            __stcs((float4*)(outB + base), vb);
            __stcs((float4*)(outL + base), vl);
            __stcs((float4*)(outC + base), vc);
        }
    }

    if (blockIdx.x == 0) {
        float* outM = out + 100663296 + b * 4096;
#pragma unroll
        for (int s = 0; s < 4; s++) {
            int p0 = (s * 256 + tid) * 4;
            int i = p0 >> 6;
            float4 v;
#pragma unroll
            for (int q = 0; q < 4; q++) {
                int j = (p0 + q) & 63;
                int o = j - i;
                ((float*)&v)[q] = ((o == 0) || mask_hit(o, i)) ? 1.0f : 0.0f;
            }
            __stcs((float4*)(outM + p0), v);
        }
    }
}

// ---------------------------------------------------------------------------
extern "C" void kernel_launch(void* const* d_in, const int* in_sizes, int n_in,
                              void* d_out, int out_size)
{
    const float* x   = (const float*)d_in[0];
    const float* w_c = (const float*)d_in[1];
    const float* b_c = (const float*)d_in[2];
    const float* w_v = (const float*)d_in[3];
    const float* b_v = (const float*)d_in[4];
    float* out = (float*)d_out;

    gemm_kq<<<dim3(8, 16), 256>>>(x, w_c, b_c, w_v, b_v);
    m2m_softmax<<<32, 128>>>();
    writer<<<dim3(32, 16), 256>>>(x, out);
}